// round 11
// baseline (speedup 1.0000x reference)
#include <cuda_runtime.h>

// x (B,L,C,H,W) = (2,24,32,128,256) fp32, params (2,C,R) = (2,32,32) fp32.
// Exact causal FIR conv along L (reference rfft(48) has no aliasing, 2L-1=47<=48).
//
// R11 = R8 with the triangular MAC transposed to t-outer / l-inner:
//   for t: kk = dup(sk[t]); for l>=t: acc[l] += kk * xv[l-t]; store y[t]
// k is materialized once per tap (24 LDS + 24 MOVs instead of ~300 each),
// FMA count unchanged; y[t] completes at iteration t so stores stay spread.
// Needs 24 live accumulators (~112 regs, 2 CTAs/SM) — occupancy proven
// irrelevant in R4/R5. Dead ends: persistence (R3), occupancy (R5),
// L2 pinning (R6/7), TMA (R9), store policy (R10).

#define B_ 2
#define L_ 24
#define C_ 32
#define H_ 128
#define W_ 256
#define R_ 32

__global__ __launch_bounds__(256, 2)
void ConvLRU_fused_kernel(const unsigned long long* __restrict__ x,
                          const float*              __restrict__ p,
                          unsigned long long*       __restrict__ y) {
    constexpr int HW2     = H_ * (W_ / 2);   // 16384 = 2^14
    constexpr int strideL = C_ * HW2;        // 524288 64-bit elems between l's

    // gid bit-layout: bits [0:14) = hw, [14:19) = c, [19] = b
    int gid = blockIdx.x * 256 + threadIdx.x;              // over 2^20
    int c   = (gid >> 14) & (C_ - 1);
    int base = gid + (gid >> 19) * ((L_ - 1) * strideL);   // 64-bit idx of l=0

    __shared__ float sk[L_];

    // ---- issue all 24 sequence loads first (deep MLP, nc + evict-first) ----
    unsigned long long xv[L_];
#pragma unroll
    for (int l = 0; l < L_; l++) {
        const unsigned long long* ptr = &x[base + l * strideL];
        asm("ld.global.nc.cs.b64 %0, [%1];" : "=l"(xv[l]) : "l"(ptr));
    }

    // ---- k[c][t] = sum_r gamma*exp(-t*nu)*cos(t*theta); hides under loads ----
    {
        int lane = threadIdx.x & 31;       // = rank r
        int wrp  = threadIdx.x >> 5;       // warp id 0..7
        float nu_log    = p[c * R_ + lane];
        float theta_log = p[C_ * R_ + c * R_ + lane];
        float nu    = __expf(nu_log);
        float theta = __expf(theta_log);
        float lam2  = __expf(-2.0f * nu);
        float gamma = sqrtf(fmaxf(1.0f - lam2, 1e-12f));
#pragma unroll
        for (int j = 0; j < 3; j++) {
            int   t  = 8 * j + wrp;        // each warp covers t = w, w+8, w+16
            float tf = (float)t;
            float term = gamma * __expf(-tf * nu) * __cosf(tf * theta);
#pragma unroll
            for (int off = 16; off > 0; off >>= 1)
                term += __shfl_xor_sync(0xFFFFFFFFu, term, off);
            if (lane == 0) sk[t] = term;
        }
    }

    __syncthreads();   // sk visible; xv loads still in flight

    // ---- t-outer triangular MAC: each tap's packed k built exactly once ----
    unsigned long long acc[L_];
#pragma unroll
    for (int l = 0; l < L_; l++) acc[l] = 0ull;

#pragma unroll
    for (int t = 0; t < L_; t++) {
        float kv = sk[t];
        unsigned long long kk;
        asm("mov.b64 %0, {%1, %1};" : "=l"(kk) : "r"(__float_as_uint(kv)));
#pragma unroll
        for (int l = t; l < L_; l++) {
            asm("fma.rn.f32x2 %0, %1, %2, %0;" : "+l"(acc[l]) : "l"(xv[l - t]), "l"(kk));
        }
        // y[t] received its final contribution this iteration
        __stcs(&y[base + t * strideL], acc[t]);
    }
}

extern "C" void kernel_launch(void* const* d_in, const int* in_sizes, int n_in,
                              void* d_out, int out_size) {
    const float* x = (const float*)d_in[0];        // (B,L,C,H,W)
    const float* p = (const float*)d_in[1];        // (2,C,R)
    float* y = (float*)d_out;

    constexpr int total2 = B_ * C_ * H_ * (W_ / 2);  // 1048576
    ConvLRU_fused_kernel<<<total2 / 256, 256>>>(
        (const unsigned long long*)x, p, (unsigned long long*)y);
}

// round 12
// speedup vs baseline: 1.1851x; 1.1851x over previous
#include <cuda_runtime.h>

// x (B,L,C,H,W) = (2,24,32,128,256) fp32, params (2,C,R) = (2,32,32) fp32.
// Exact causal FIR conv along L (reference rfft(48) has no aliasing, 2L-1=47<=48).
//
// R12 = R8 (best l-outer config, ~80 regs, 3 CTAs/SM) with the 24-load burst
// software-pipelined into two batches of 12: y[0..11] depends only on batch 1,
// so its MAC + stores overlap batch 2's DRAM latency. Halves MLP_p1 (24->12),
// shrinking the cross-CTA L1tex-queue spread term.
// Dead ends: persistence (R3), occupancy (R5), L2 pinning (R6/7), TMA (R9),
// store policy (R10), t-outer transpose (R11: spilled).

#define B_ 2
#define L_ 24
#define C_ 32
#define H_ 128
#define W_ 256
#define R_ 32
#define LH 12                            // half of L

__global__ __launch_bounds__(256, 3)
void ConvLRU_fused_kernel(const unsigned long long* __restrict__ x,
                          const float*              __restrict__ p,
                          unsigned long long*       __restrict__ y) {
    constexpr int HW2     = H_ * (W_ / 2);   // 16384 = 2^14
    constexpr int strideL = C_ * HW2;        // 524288 64-bit elems between l's

    // gid bit-layout: bits [0:14) = hw, [14:19) = c, [19] = b
    int gid = blockIdx.x * 256 + threadIdx.x;              // over 2^20
    int c   = (gid >> 14) & (C_ - 1);
    int base = gid + (gid >> 19) * ((L_ - 1) * strideL);   // 64-bit idx of l=0

    __shared__ float sk[L_];

    unsigned long long xv[L_];

    // ---- batch 1: loads for l = 0..11 ----
#pragma unroll
    for (int l = 0; l < LH; l++) {
        const unsigned long long* ptr = &x[base + l * strideL];
        asm("ld.global.nc.cs.b64 %0, [%1];" : "=l"(xv[l]) : "l"(ptr));
    }

    // ---- k[c][t] = sum_r gamma*exp(-t*nu)*cos(t*theta); hides under batch 1 ----
    {
        int lane = threadIdx.x & 31;       // = rank r
        int wrp  = threadIdx.x >> 5;       // warp id 0..7
        float nu_log    = p[c * R_ + lane];
        float theta_log = p[C_ * R_ + c * R_ + lane];
        float nu    = __expf(nu_log);
        float theta = __expf(theta_log);
        float lam2  = __expf(-2.0f * nu);
        float gamma = sqrtf(fmaxf(1.0f - lam2, 1e-12f));
#pragma unroll
        for (int j = 0; j < 3; j++) {
            int   t  = 8 * j + wrp;        // each warp covers t = w, w+8, w+16
            float tf = (float)t;
            float term = gamma * __expf(-tf * nu) * __cosf(tf * theta);
#pragma unroll
            for (int off = 16; off > 0; off >>= 1)
                term += __shfl_xor_sync(0xFFFFFFFFu, term, off);
            if (lane == 0) sk[t] = term;
        }
    }

    __syncthreads();   // sk visible; batch-1 loads still in flight

    // ---- batch 2: loads for l = 12..23 (in flight during first MAC half) ----
#pragma unroll
    for (int l = LH; l < L_; l++) {
        const unsigned long long* ptr = &x[base + l * strideL];
        asm("ld.global.nc.cs.b64 %0, [%1];" : "=l"(xv[l]) : "l"(ptr));
    }

    // ---- first half: y[0..11] uses only batch 1; overlaps batch-2 latency ----
#pragma unroll
    for (int l = 0; l < LH; l++) {
        unsigned long long acc = 0ull;     // {0.f, 0.f}
#pragma unroll
        for (int t = 0; t <= l; t++) {
            float kv = sk[t];
            unsigned long long kk;
            asm("mov.b64 %0, {%1, %1};" : "=l"(kk) : "r"(__float_as_uint(kv)));
            asm("fma.rn.f32x2 %0, %1, %2, %0;" : "+l"(acc) : "l"(xv[l - t]), "l"(kk));
        }
        __stcs(&y[base + l * strideL], acc);
    }

    // ---- second half: y[12..23] (needs batch 2) ----
#pragma unroll
    for (int l = LH; l < L_; l++) {
        unsigned long long acc = 0ull;
#pragma unroll
        for (int t = 0; t <= l; t++) {
            float kv = sk[t];
            unsigned long long kk;
            asm("mov.b64 %0, {%1, %1};" : "=l"(kk) : "r"(__float_as_uint(kv)));
            asm("fma.rn.f32x2 %0, %1, %2, %0;" : "+l"(acc) : "l"(xv[l - t]), "l"(kk));
        }
        __stcs(&y[base + l * strideL], acc);
    }
}

extern "C" void kernel_launch(void* const* d_in, const int* in_sizes, int n_in,
                              void* d_out, int out_size) {
    const float* x = (const float*)d_in[0];        // (B,L,C,H,W)
    const float* p = (const float*)d_in[1];        // (2,C,R)
    float* y = (float*)d_out;

    constexpr int total2 = B_ * C_ * H_ * (W_ / 2);  // 1048576
    ConvLRU_fused_kernel<<<total2 / 256, 256>>>(
        (const unsigned long long*)x, p, (unsigned long long*)y);
}

// round 13
// speedup vs baseline: 1.1959x; 1.0091x over previous
#include <cuda_runtime.h>

// x (B,L,C,H,W) = (2,24,32,128,256) fp32, params (2,C,R) = (2,32,32) fp32.
// Exact causal FIR conv along L (reference rfft(48) has no aliasing, 2L-1=47<=48).
//
// R13 = R8 (best: 63.55us) with k stored PRE-DUPLICATED as 64-bit in smem
// (sk2[t] = {k,k}), so the MAC inner body is LDS.64 + fma.rn.f32x2 with no
// per-iteration mov.b64 duplication (~300 MOVs/thread removed).
// Converged config: 64-bit elems/thread, 3 CTAs/SM, loads-first (.nc.cs),
// k-compute hidden under loads, streaming stores.
// Dead ends: persistence (R3), occupancy (R5), L2 pinning (R6/7), TMA (R9),
// store policy (R10), t-outer (R11: spills), split batches (R12).

#define B_ 2
#define L_ 24
#define C_ 32
#define H_ 128
#define W_ 256
#define R_ 32

__global__ __launch_bounds__(256, 3)
void ConvLRU_fused_kernel(const unsigned long long* __restrict__ x,
                          const float*              __restrict__ p,
                          unsigned long long*       __restrict__ y) {
    constexpr int HW2     = H_ * (W_ / 2);   // 16384 = 2^14
    constexpr int strideL = C_ * HW2;        // 524288 64-bit elems between l's

    // gid bit-layout: bits [0:14) = hw, [14:19) = c, [19] = b
    int gid = blockIdx.x * 256 + threadIdx.x;              // over 2^20
    int c   = (gid >> 14) & (C_ - 1);
    int base = gid + (gid >> 19) * ((L_ - 1) * strideL);   // 64-bit idx of l=0

    __shared__ float2 sk2[L_];   // k duplicated into both halves at write time

    // ---- issue all 24 sequence loads first (deep MLP, nc + evict-first) ----
    unsigned long long xv[L_];
#pragma unroll
    for (int l = 0; l < L_; l++) {
        const unsigned long long* ptr = &x[base + l * strideL];
        asm("ld.global.nc.cs.b64 %0, [%1];" : "=l"(xv[l]) : "l"(ptr));
    }

    // ---- k[c][t] = sum_r gamma*exp(-t*nu)*cos(t*theta); hides under loads ----
    {
        int lane = threadIdx.x & 31;       // = rank r
        int wrp  = threadIdx.x >> 5;       // warp id 0..7
        float nu_log    = p[c * R_ + lane];
        float theta_log = p[C_ * R_ + c * R_ + lane];
        float nu    = __expf(nu_log);
        float theta = __expf(theta_log);
        float lam2  = __expf(-2.0f * nu);
        float gamma = sqrtf(fmaxf(1.0f - lam2, 1e-12f));
#pragma unroll
        for (int j = 0; j < 3; j++) {
            int   t  = 8 * j + wrp;        // each warp covers t = w, w+8, w+16
            float tf = (float)t;
            float term = gamma * __expf(-tf * nu) * __cosf(tf * theta);
#pragma unroll
            for (int off = 16; off > 0; off >>= 1)
                term += __shfl_xor_sync(0xFFFFFFFFu, term, off);
            if (lane == 0) sk2[t] = make_float2(term, term);   // pre-duplicated
        }
    }

    __syncthreads();   // sk2 visible; xv loads still in flight

    // ---- triangular causal MAC: LDS.64 + packed FMA, no per-iter dup ----
#pragma unroll
    for (int l = 0; l < L_; l++) {
        unsigned long long acc = 0ull;     // {0.f, 0.f}
#pragma unroll
        for (int t = 0; t <= l; t++) {
            unsigned long long kk = *reinterpret_cast<unsigned long long*>(&sk2[t]);
            asm("fma.rn.f32x2 %0, %1, %2, %0;" : "+l"(acc) : "l"(xv[l - t]), "l"(kk));
        }
        __stcs(&y[base + l * strideL], acc);
    }
}

extern "C" void kernel_launch(void* const* d_in, const int* in_sizes, int n_in,
                              void* d_out, int out_size) {
    const float* x = (const float*)d_in[0];        // (B,L,C,H,W)
    const float* p = (const float*)d_in[1];        // (2,C,R)
    float* y = (float*)d_out;

    constexpr int total2 = B_ * C_ * H_ * (W_ / 2);  // 1048576
    ConvLRU_fused_kernel<<<total2 / 256, 256>>>(
        (const unsigned long long*)x, p, (unsigned long long*)y);
}